// round 12
// baseline (speedup 1.0000x reference)
#include <cuda_runtime.h>
#include <cuda_bf16.h>
#include <cstdint>

// Problem constants
#define U_DIM 20000
#define I_DIM 10000
#define K_DIM 64
#define B_DIM 4096

// Output regions (floats), reference return order.
#define OFF_SHAT   0LL
#define N_SHAT     (200000000LL)                 // U*I
#define OFF_UF     (OFF_SHAT + N_SHAT)           // 200,000,000
#define N_UF       (1280000LL)
#define OFF_UB     (OFF_UF + N_UF)               // 201,280,000
#define N_UB       (20000LL)
#define OFF_IF     (OFF_UB + N_UB)               // 201,300,000
#define N_IF       (640000LL)
#define OFF_IB     (OFF_IF + N_IF)               // 201,940,000
#define N_IB       (10000LL)
#define N_TOTAL    (OFF_IB + N_IB)               // 201,950,000 (divisible by 4)

#define ZTHREADS   256
#define VPT        4        // float4 stores per thread (64 B/thread)

// ---------------------------------------------------------------------------
// Kernel 1: zero the whole output. PURE fire-and-forget float4 stores — no
// loads, no fences, no atomics, no PDL trigger (R5/R6/R8 proved any memory-
// ordering op or dependent load here halves store bandwidth).
// 4 coalesced stores per thread: thread t of block b writes float4 indices
// base+t, base+256, base+512, base+768 (4 consecutive 4KB segments) —
// front-batched STGs (MLP_p1=4), 4x fewer CTAs than the 1-store variant.
// ---------------------------------------------------------------------------
__global__ void __launch_bounds__(ZTHREADS)
mmf_zero_kernel(float4* __restrict__ out, long long n4) {
    long long base = (long long)blockIdx.x * (ZTHREADS * VPT) + threadIdx.x;
    const float4 z = make_float4(0.f, 0.f, 0.f, 0.f);
    #pragma unroll
    for (int k = 0; k < VPT; ++k) {
        long long idx = base + (long long)k * ZTHREADS;
        if (idx < n4) out[idx] = z;
    }
}

__device__ __forceinline__ float warp_sum(float s) {
    #pragma unroll
    for (int off = 16; off; off >>= 1)
        s += __shfl_xor_sync(0xffffffffu, s, off);
    return s;
}

// ---------------------------------------------------------------------------
// Kernel 2 (PDL, implicit trigger): one warp per batch entry. Prologue:
// index loads, random row gathers, dot product, bias loads. Then
// cudaGridDependencySynchronize() (sweep's zeros visible), then the
// scattered stores. Duplicate u/i/(u,i) write identical values (benign).
// Proven 5.8us shape — unchanged from R10.
// ---------------------------------------------------------------------------
__global__ void __launch_bounds__(256)
mmf_scatter_pdl(const float* __restrict__ P,   // [U,K]
                const float* __restrict__ Q,   // [I,K]
                const float* __restrict__ bu,  // [U]
                const float* __restrict__ bi,  // [I]
                const int* __restrict__ uidx,  // [B] i32
                const int* __restrict__ iidx,  // [B] i32
                float* __restrict__ out) {
    int g    = blockIdx.x * blockDim.x + threadIdx.x;
    int e    = g >> 5;                         // entry = warp id
    int lane = g & 31;

    // ---- phase 1: all loads + compute ----
    int u = __ldg(&uidx[e]);
    int i = __ldg(&iidx[e]);

    const float2* pu = reinterpret_cast<const float2*>(P + (long long)u * K_DIM);
    const float2* qi = reinterpret_cast<const float2*>(Q + (long long)i * K_DIM);
    float2 a = __ldg(&pu[lane]);
    float2 b = __ldg(&qi[lane]);

    float s = warp_sum(fmaf(a.x, b.x, a.y * b.y));
    float bias_u = __ldg(&bu[u]);
    float bias_i = __ldg(&bi[i]);

    float2* uf  = reinterpret_cast<float2*>(out + OFF_UF + (long long)u * K_DIM);
    float2* ifr = reinterpret_cast<float2*>(out + OFF_IF + (long long)i * K_DIM);

    // ---- wait for the sweep's stores to be globally visible ----
    cudaGridDependencySynchronize();

    // ---- phase 2: scattered stores ----
    uf[lane]  = a;
    ifr[lane] = b;
    if (lane == 0) {
        out[OFF_UB + u] = bias_u;
        out[OFF_IB + i] = bias_i;
        out[(long long)u * I_DIM + i] = s + bias_u + bias_i;
    }
}

// ---------------------------------------------------------------------------
// Launch. inputs: P [U,K] f32, Q [I,K] f32, bu [U,1] f32, bi [I] f32,
// users_idx [B] int32, items_idx [B] int32
// ---------------------------------------------------------------------------
extern "C" void kernel_launch(void* const* d_in, const int* in_sizes, int n_in,
                              void* d_out, int out_size) {
    const float* P    = (const float*)d_in[0];
    const float* Q    = (const float*)d_in[1];
    const float* bu   = (const float*)d_in[2];
    const float* bi   = (const float*)d_in[3];
    const int*   uidx = (const int*)d_in[4];
    const int*   iidx = (const int*)d_in[5];
    float* out = (float*)d_out;

    // 1) zero everything (808 MB pure stores — the roofline)
    const long long n_total = (long long)out_size;   // 201,950,000
    const long long n4 = n_total / 4;                // divides exactly
    const long long per_blk = ZTHREADS * VPT;        // 1024 float4s per block
    const long long zblocks = (n4 + per_blk - 1) / per_blk;   // 49,305
    mmf_zero_kernel<<<(unsigned)zblocks, ZTHREADS>>>((float4*)out, n4);

    // 2) scatter with PDL (implicit trigger)
    cudaLaunchConfig_t cfg = {};
    cfg.gridDim  = dim3((B_DIM * 32) / 256, 1, 1);   // 512 blocks
    cfg.blockDim = dim3(256, 1, 1);
    cudaLaunchAttribute attrs[1];
    attrs[0].id = cudaLaunchAttributeProgrammaticStreamSerialization;
    attrs[0].val.programmaticStreamSerializationAllowed = 1;
    cfg.attrs = attrs;
    cfg.numAttrs = 1;
    cudaLaunchKernelEx(&cfg, mmf_scatter_pdl, P, Q, bu, bi, uidx, iidx, out);
}